// round 8
// baseline (speedup 1.0000x reference)
#include <cuda_runtime.h>
#include <cuda_fp16.h>
#include <stdint.h>
#include <math.h>

#define NHALF 2048
#define NTOT  4096
#define DDIM  512

#define BM 128
#define BN 128
#define BK 32
#define NCHUNK (DDIM / BK)   // 16
#define NTILE 32
#define NBLK 528             // upper-triangle tiles

#define TPAD 40                      // fp16 elements per smem tile row (80 B)
#define TILE_B (128 * TPAD * 2)      // 10240 B per tile
#define STAGE_B (4 * TILE_B)         // Ah, Al, Bh, Bl
#define SM_TOTAL (2 * STAGE_B)       // 81920 B (dist tile overlays this)
#define DPAD 133                     // fp32 dist tile row stride

// ---------------- device globals ----------------
__device__ float     g_sq[NTOT];
__device__ unsigned  g_negmin_bits[NTOT];
__device__ float     g_pos[NTOT];
__device__ __half    g_hi[NTOT * DDIM];
__device__ __half    g_lo[NTOT * DDIM];

// ---------------- helpers ----------------
__device__ __forceinline__ uint32_t smem_u32(const void* p) {
    uint32_t a;
    asm("{ .reg .u64 t; cvta.to.shared.u64 t, %1; cvt.u32.u64 %0, t; }"
        : "=r"(a) : "l"(p));
    return a;
}
__device__ __forceinline__ void cp16(uint32_t dst, const void* src) {
    asm volatile("cp.async.cg.shared.global [%0], [%1], 16;"
                 :: "r"(dst), "l"(src));
}
#define CP_COMMIT() asm volatile("cp.async.commit_group;" ::: "memory")
#define CP_WAIT1()  asm volatile("cp.async.wait_group 1;" ::: "memory")
#define CP_WAIT0()  asm volatile("cp.async.wait_group 0;" ::: "memory")

__device__ __forceinline__ void ldx4(uint32_t* r, uint32_t addr) {
    asm volatile("ldmatrix.sync.aligned.m8n8.x4.shared.b16 {%0,%1,%2,%3}, [%4];"
                 : "=r"(r[0]), "=r"(r[1]), "=r"(r[2]), "=r"(r[3]) : "r"(addr));
}
// fp32-accumulate fp16 MMA (hi*hi pass)
__device__ __forceinline__ void mma_f32acc(float* d, const uint32_t* a,
                                           const uint32_t* b) {
    asm volatile(
        "mma.sync.aligned.m16n8k16.row.col.f32.f16.f16.f32 "
        "{%0,%1,%2,%3}, {%4,%5,%6,%7}, {%8,%9}, {%0,%1,%2,%3};"
        : "+f"(d[0]), "+f"(d[1]), "+f"(d[2]), "+f"(d[3])
        : "r"(a[0]), "r"(a[1]), "r"(a[2]), "r"(a[3]), "r"(b[0]), "r"(b[1]));
}
// fp16-accumulate fp16 MMA (cross terms; 2x rate on legacy tensor pipe)
__device__ __forceinline__ void mma_f16acc(uint32_t* d, const uint32_t* a,
                                           const uint32_t* b) {
    asm volatile(
        "mma.sync.aligned.m16n8k16.row.col.f16.f16.f16.f16 "
        "{%0,%1}, {%2,%3,%4,%5}, {%6,%7}, {%0,%1};"
        : "+r"(d[0]), "+r"(d[1])
        : "r"(a[0]), "r"(a[1]), "r"(a[2]), "r"(a[3]), "r"(b[0]), "r"(b[1]));
}

// ---------------------------------------------------------------------------
// Kernel 1: row sums of squares + fp16 hi/lo split + scratch reset
// ---------------------------------------------------------------------------
__global__ void prep_kernel(const float* __restrict__ h1,
                            const float* __restrict__ h2) {
    int r = blockIdx.x;
    const float* src = (r < NHALF) ? (h1 + (size_t)r * DDIM)
                                   : (h2 + (size_t)(r - NHALF) * DDIM);
    int t = threadIdx.x;  // 0..127
    float4 v = ((const float4*)src)[t];
    float s = v.x * v.x + v.y * v.y + v.z * v.z + v.w * v.w;

    float xs[4] = {v.x, v.y, v.z, v.w};
    __half hh[4], ll[4];
    #pragma unroll
    for (int i = 0; i < 4; i++) {
        hh[i] = __float2half_rn(xs[i]);
        ll[i] = __float2half_rn(xs[i] - __half2float(hh[i]));
    }
    size_t base = (size_t)r * DDIM + 4 * t;
    __half2* gh = (__half2*)(g_hi + base);
    gh[0] = __half2(hh[0], hh[1]);
    gh[1] = __half2(hh[2], hh[3]);
    __half2* gl = (__half2*)(g_lo + base);
    gl[0] = __half2(ll[0], ll[1]);
    gl[1] = __half2(ll[2], ll[3]);

    #pragma unroll
    for (int off = 16; off > 0; off >>= 1)
        s += __shfl_xor_sync(0xffffffffu, s, off);

    __shared__ float warp_s[4];
    int lane = t & 31, wid = t >> 5;
    if (lane == 0) warp_s[wid] = s;
    __syncthreads();
    if (t == 0) {
        g_sq[r] = warp_s[0] + warp_s[1] + warp_s[2] + warp_s[3];
        g_negmin_bits[r] = 0x7f800000u;  // +inf
        g_pos[r] = 0.0f;
    }
}

// ---------------------------------------------------------------------------
// async-load one pipeline stage (4 tiles of 128 x 32 fp16)
// ---------------------------------------------------------------------------
__device__ __forceinline__ void load_stage(uint32_t smb, int stage,
                                           const __half* ah, const __half* al,
                                           const __half* bh, const __half* bl,
                                           int k0, int tid) {
    const __half* srcs[4] = {ah, al, bh, bl};
    uint32_t base = smb + stage * STAGE_B;
    #pragma unroll
    for (int t = 0; t < 4; t++) {
        #pragma unroll
        for (int i = 0; i < 2; i++) {
            int chunk = tid * 2 + i;       // 0..511
            int r = chunk >> 2;            // 0..127
            int c = chunk & 3;             // 16B chunk within 64B row
            cp16(base + t * TILE_B + r * (TPAD * 2) + c * 16,
                 srcs[t] + (size_t)r * DDIM + k0 + c * 8);
        }
    }
}

// ---------------------------------------------------------------------------
// Kernel 2: fp16x2-split mma.sync X*X^T (upper triangle) + distance epilogue
// ---------------------------------------------------------------------------
__global__ __launch_bounds__(256, 2)
void gemm_dist_kernel() {
    extern __shared__ char smem[];
    const uint32_t smb = smem_u32(smem);
    const int tid = threadIdx.x;
    const int wid = tid >> 5, lane = tid & 31;

    // decode upper-triangle tile index
    int t = blockIdx.x;
    int bi = 0;
    while (t >= NTILE - bi) { t -= NTILE - bi; bi++; }
    const int bj = bi + t;
    const int row0 = bi * BM;
    const int col0 = bj * BN;
    const bool isdiag = (bi == bj);

    const __half* Ah_g = g_hi + (size_t)row0 * DDIM;
    const __half* Al_g = g_lo + (size_t)row0 * DDIM;
    const __half* Bh_g = g_hi + (size_t)col0 * DDIM;
    const __half* Bl_g = g_lo + (size_t)col0 * DDIM;

    // warp tile: 32 (M) x 64 (N)
    const int wm = wid & 3, wn = wid >> 2;
    const int m0 = wm * 32, n0 = wn * 64;

    float acc[2][8][4];          // hi*hi, fp32 acc
    uint32_t accx[2][8][2];      // hi*lo + lo*hi, fp16 acc (4 halves)
    #pragma unroll
    for (int i = 0; i < 2; i++)
        #pragma unroll
        for (int j = 0; j < 8; j++) {
            #pragma unroll
            for (int q = 0; q < 4; q++) acc[i][j][q] = 0.0f;
            accx[i][j][0] = 0u;
            accx[i][j][1] = 0u;
        }

    // ldmatrix lane addressing
    const int arow = (lane & 7) + ((lane >> 3) & 1) * 8;
    const int acol = (lane >> 4) * 8;
    const int brow = (lane & 7) + ((lane >> 4) << 3);
    const int bcol = ((lane >> 3) & 1) * 8;

    load_stage(smb, 0, Ah_g, Al_g, Bh_g, Bl_g, 0, tid);
    CP_COMMIT();

    for (int it = 0; it < NCHUNK; it++) {
        if (it + 1 < NCHUNK) {
            load_stage(smb, (it + 1) & 1, Ah_g, Al_g, Bh_g, Bl_g,
                       (it + 1) * BK, tid);
            CP_COMMIT();
            CP_WAIT1();
        } else {
            CP_WAIT0();
        }
        __syncthreads();

        const uint32_t Ah = smb + (it & 1) * STAGE_B;
        const uint32_t Al = Ah + TILE_B;
        const uint32_t Bh = Al + TILE_B;
        const uint32_t Bl = Bh + TILE_B;

        #pragma unroll
        for (int ks = 0; ks < 2; ks++) {
            const int kb = ks * 16;
            uint32_t ahr[2][4], alr[2][4];
            #pragma unroll
            for (int mt = 0; mt < 2; mt++) {
                uint32_t off = (uint32_t)(m0 + mt * 16 + arow) * (TPAD * 2)
                             + (kb + acol) * 2;
                ldx4(ahr[mt], Ah + off);
                ldx4(alr[mt], Al + off);
            }
            // stream B per 16-col group to limit register pressure
            #pragma unroll
            for (int p = 0; p < 4; p++) {
                uint32_t off = (uint32_t)(n0 + p * 16 + brow) * (TPAD * 2)
                             + (kb + bcol) * 2;
                uint32_t rh[4], rl[4];
                ldx4(rh, Bh + off);
                ldx4(rl, Bl + off);
                uint32_t b0h[2] = {rh[0], rh[1]}, b1h[2] = {rh[2], rh[3]};
                uint32_t b0l[2] = {rl[0], rl[1]}, b1l[2] = {rl[2], rl[3]};
                #pragma unroll
                for (int mt = 0; mt < 2; mt++) {
                    mma_f32acc(acc[mt][2 * p],     ahr[mt], b0h);
                    mma_f32acc(acc[mt][2 * p + 1], ahr[mt], b1h);
                    mma_f16acc(accx[mt][2 * p],     ahr[mt], b0l);
                    mma_f16acc(accx[mt][2 * p + 1], ahr[mt], b1l);
                    mma_f16acc(accx[mt][2 * p],     alr[mt], b0h);
                    mma_f16acc(accx[mt][2 * p + 1], alr[mt], b1h);
                }
            }
        }
        __syncthreads();
    }

    // ---------------- epilogue: dots -> smem dist tile ----------------
    float* ds = (float*)smem;
    const int g = lane >> 2;
    const int cl = (lane & 3) * 2;
    #pragma unroll
    for (int mt = 0; mt < 2; mt++) {
        const int rb = m0 + mt * 16 + g;
        #pragma unroll
        for (int nt = 0; nt < 8; nt++) {
            const int cb = n0 + nt * 8 + cl;
            __half2 x01 = *(__half2*)&accx[mt][nt][0];
            __half2 x23 = *(__half2*)&accx[mt][nt][1];
            ds[rb * DPAD + cb]           = acc[mt][nt][0] + __half2float(x01.x);
            ds[rb * DPAD + cb + 1]       = acc[mt][nt][1] + __half2float(x01.y);
            ds[(rb + 8) * DPAD + cb]     = acc[mt][nt][2] + __half2float(x23.x);
            ds[(rb + 8) * DPAD + cb + 1] = acc[mt][nt][3] + __half2float(x23.y);
        }
    }
    __syncthreads();

    const float INF = __int_as_float(0x7f800000);
    if (tid < 128) {
        // row pass: hardest positive + row min
        const int gi = row0 + tid;
        const float si = g_sq[gi];
        const int partner = (gi < NHALF) ? (gi + NHALF) : (gi - NHALF);
        float mn = INF;
        for (int c = 0; c < 128; c++) {
            const int gj = col0 + c;
            float dot = ds[tid * DPAD + c];
            float d2 = si + g_sq[gj] - 2.0f * dot;
            float dist = fmaxf(sqrtf(fmaxf(d2, 1e-14f)), 1e-7f);
            if (gj == partner) {
                g_pos[gi] = dist;
                g_pos[gj] = dist;
            } else if (gj != gi) {
                mn = fminf(mn, dist);
            }
        }
        atomicMin(&g_negmin_bits[gi], __float_as_uint(mn));
    } else if (!isdiag) {
        // col pass: col min (off-diagonal tiles only)
        const int c = tid - 128;
        const int gj = col0 + c;
        const float sj = g_sq[gj];
        const int partner = (gj < NHALF) ? (gj + NHALF) : (gj - NHALF);
        float mn = INF;
        for (int r = 0; r < 128; r++) {
            const int gi = row0 + r;
            float dot = ds[r * DPAD + c];
            float d2 = sj + g_sq[gi] - 2.0f * dot;
            float dist = fmaxf(sqrtf(fmaxf(d2, 1e-14f)), 1e-7f);
            if (gi != partner && gi != gj)
                mn = fminf(mn, dist);
        }
        atomicMin(&g_negmin_bits[gj], __float_as_uint(mn));
    }
}

// ---------------------------------------------------------------------------
// Kernel 3: finalize (single block)
// ---------------------------------------------------------------------------
__global__ void finalize_kernel(float* __restrict__ out) {
    const int t = threadIdx.x;  // 256 threads
    float sumdiff = 0.0f, sumrel = 0.0f, sumsq = 0.0f;
    int nrel = 0, good = 0;

    for (int r = t; r < NTOT; r += 256) {
        float pos = g_pos[r];
        float neg = __uint_as_float(g_negmin_bits[r]);
        float diff = pos - neg;
        float tl = fmaxf(diff + 0.1f, 0.0f);
        sumdiff += diff;
        if (tl > 1e-5f) { sumrel += tl; nrel++; }
        if (tl < 1e-5f) good++;
        sumsq += g_sq[r];
    }

    __shared__ float s_diff[256], s_rel[256], s_sq[256];
    __shared__ int   s_nrel[256], s_good[256];
    s_diff[t] = sumdiff; s_rel[t] = sumrel; s_sq[t] = sumsq;
    s_nrel[t] = nrel;    s_good[t] = good;
    __syncthreads();

    for (int stride = 128; stride > 0; stride >>= 1) {
        if (t < stride) {
            s_diff[t] += s_diff[t + stride];
            s_rel[t]  += s_rel[t + stride];
            s_sq[t]   += s_sq[t + stride];
            s_nrel[t] += s_nrel[t + stride];
            s_good[t] += s_good[t + stride];
        }
        __syncthreads();
    }

    if (t == 0) {
        int n_rel = s_nrel[0] > 0 ? s_nrel[0] : 1;
        out[0] = s_rel[0] / (float)n_rel;
        out[1] = s_diff[0] / (float)NTOT;
        out[2] = (float)s_good[0];
        out[3] = (float)(NTOT - s_good[0]);
        out[4] = sqrtf(s_sq[0] / (float)NTOT);
    }
}

// ---------------------------------------------------------------------------
extern "C" void kernel_launch(void* const* d_in, const int* in_sizes, int n_in,
                              void* d_out, int out_size) {
    const float* h1 = (const float*)d_in[0];
    const float* h2 = (const float*)d_in[1];
    float* out = (float*)d_out;

    cudaFuncSetAttribute(gemm_dist_kernel,
                         cudaFuncAttributeMaxDynamicSharedMemorySize, SM_TOTAL);

    prep_kernel<<<NTOT, 128>>>(h1, h2);
    gemm_dist_kernel<<<NBLK, 256, SM_TOTAL>>>();
    finalize_kernel<<<1, 256>>>(out);
}

// round 9
// speedup vs baseline: 1.0214x; 1.0214x over previous
#include <cuda_runtime.h>
#include <cuda_bf16.h>
#include <stdint.h>
#include <math.h>

#define NHALF 2048
#define NTOT  4096
#define DDIM  512

#define BM 128
#define BN 128
#define BK 32
#define NCHUNK (DDIM / BK)   // 16
#define NTILE 32
#define NBLK 528             // upper-triangle tiles

#define TPAD 40                      // bf16 elements per smem tile row (80 B)
#define TILE_B (128 * TPAD * 2)      // 10240 B per tile
#define STAGE_B (4 * TILE_B)         // Ah, Al, Bh, Bl
#define SM_TOTAL (2 * STAGE_B)       // 81920 B (dist tile overlays this)
#define DPAD 133                     // fp32 dist tile row stride

// ---------------- device globals ----------------
__device__ float          g_sq[NTOT];
__device__ unsigned       g_negmin_bits[NTOT];
__device__ float          g_pos[NTOT];
__device__ __nv_bfloat16  g_hi[NTOT * DDIM];
__device__ __nv_bfloat16  g_lo[NTOT * DDIM];

// ---------------- helpers ----------------
__device__ __forceinline__ uint32_t smem_u32(const void* p) {
    uint32_t a;
    asm("{ .reg .u64 t; cvta.to.shared.u64 t, %1; cvt.u32.u64 %0, t; }"
        : "=r"(a) : "l"(p));
    return a;
}
__device__ __forceinline__ void cp16(uint32_t dst, const void* src) {
    asm volatile("cp.async.cg.shared.global [%0], [%1], 16;"
                 :: "r"(dst), "l"(src));
}
#define CP_COMMIT() asm volatile("cp.async.commit_group;" ::: "memory")
#define CP_WAIT1()  asm volatile("cp.async.wait_group 1;" ::: "memory")
#define CP_WAIT0()  asm volatile("cp.async.wait_group 0;" ::: "memory")

__device__ __forceinline__ void ldx4(uint32_t* r, uint32_t addr) {
    asm volatile("ldmatrix.sync.aligned.m8n8.x4.shared.b16 {%0,%1,%2,%3}, [%4];"
                 : "=r"(r[0]), "=r"(r[1]), "=r"(r[2]), "=r"(r[3]) : "r"(addr));
}
__device__ __forceinline__ void mma16816(float* d, const uint32_t* a,
                                         const uint32_t* b) {
    asm volatile(
        "mma.sync.aligned.m16n8k16.row.col.f32.bf16.bf16.f32 "
        "{%0,%1,%2,%3}, {%4,%5,%6,%7}, {%8,%9}, {%0,%1,%2,%3};"
        : "+f"(d[0]), "+f"(d[1]), "+f"(d[2]), "+f"(d[3])
        : "r"(a[0]), "r"(a[1]), "r"(a[2]), "r"(a[3]), "r"(b[0]), "r"(b[1]));
}

// ---------------------------------------------------------------------------
// Kernel 1: row sums of squares + bf16 hi/lo split + scratch reset
// ---------------------------------------------------------------------------
__global__ void prep_kernel(const float* __restrict__ h1,
                            const float* __restrict__ h2) {
    int r = blockIdx.x;
    const float* src = (r < NHALF) ? (h1 + (size_t)r * DDIM)
                                   : (h2 + (size_t)(r - NHALF) * DDIM);
    int t = threadIdx.x;  // 0..127
    float4 v = ((const float4*)src)[t];
    float s = v.x * v.x + v.y * v.y + v.z * v.z + v.w * v.w;

    __nv_bfloat16 a0 = __float2bfloat16(v.x);
    __nv_bfloat16 a1 = __float2bfloat16(v.y);
    __nv_bfloat16 a2 = __float2bfloat16(v.z);
    __nv_bfloat16 a3 = __float2bfloat16(v.w);
    __nv_bfloat16 l0 = __float2bfloat16(v.x - __bfloat162float(a0));
    __nv_bfloat16 l1 = __float2bfloat16(v.y - __bfloat162float(a1));
    __nv_bfloat16 l2 = __float2bfloat16(v.z - __bfloat162float(a2));
    __nv_bfloat16 l3 = __float2bfloat16(v.w - __bfloat162float(a3));

    size_t base = (size_t)r * DDIM + 4 * t;
    __nv_bfloat162* gh = (__nv_bfloat162*)(g_hi + base);
    gh[0] = __nv_bfloat162(a0, a1);
    gh[1] = __nv_bfloat162(a2, a3);
    __nv_bfloat162* gl = (__nv_bfloat162*)(g_lo + base);
    gl[0] = __nv_bfloat162(l0, l1);
    gl[1] = __nv_bfloat162(l2, l3);

    #pragma unroll
    for (int off = 16; off > 0; off >>= 1)
        s += __shfl_xor_sync(0xffffffffu, s, off);

    __shared__ float warp_s[4];
    int lane = t & 31, wid = t >> 5;
    if (lane == 0) warp_s[wid] = s;
    __syncthreads();
    if (t == 0) {
        g_sq[r] = warp_s[0] + warp_s[1] + warp_s[2] + warp_s[3];
        g_negmin_bits[r] = 0x7f800000u;  // +inf
        g_pos[r] = 0.0f;
    }
}

// ---------------------------------------------------------------------------
// async-load one pipeline stage (4 tiles of 128 x 32 bf16)
// ---------------------------------------------------------------------------
__device__ __forceinline__ void load_stage(uint32_t smb, int stage,
                                           const __nv_bfloat16* ah,
                                           const __nv_bfloat16* al,
                                           const __nv_bfloat16* bh,
                                           const __nv_bfloat16* bl,
                                           int k0, int tid) {
    const __nv_bfloat16* srcs[4] = {ah, al, bh, bl};
    uint32_t base = smb + stage * STAGE_B;
    #pragma unroll
    for (int t = 0; t < 4; t++) {
        #pragma unroll
        for (int i = 0; i < 2; i++) {
            int chunk = tid * 2 + i;       // 0..511
            int r = chunk >> 2;            // 0..127
            int c = chunk & 3;             // 16B chunk within 64B row
            cp16(base + t * TILE_B + r * (TPAD * 2) + c * 16,
                 srcs[t] + (size_t)r * DDIM + k0 + c * 8);
        }
    }
}

// ---------------------------------------------------------------------------
// Kernel 2: bf16x3 mma.sync X*X^T (upper triangle) + fused distance epilogue
//   inner loop: p-pair processing, 3 grouped passes over 8 distinct accs
//   -> every accumulator reused at distance 8 MMAs (hides HMMA latency)
// ---------------------------------------------------------------------------
__global__ __launch_bounds__(256, 2)
void gemm_dist_kernel() {
    extern __shared__ char smem[];
    const uint32_t smb = smem_u32(smem);
    const int tid = threadIdx.x;
    const int wid = tid >> 5, lane = tid & 31;

    // decode upper-triangle tile index
    int t = blockIdx.x;
    int bi = 0;
    while (t >= NTILE - bi) { t -= NTILE - bi; bi++; }
    const int bj = bi + t;
    const int row0 = bi * BM;
    const int col0 = bj * BN;
    const bool isdiag = (bi == bj);

    const __nv_bfloat16* Ah_g = g_hi + (size_t)row0 * DDIM;
    const __nv_bfloat16* Al_g = g_lo + (size_t)row0 * DDIM;
    const __nv_bfloat16* Bh_g = g_hi + (size_t)col0 * DDIM;
    const __nv_bfloat16* Bl_g = g_lo + (size_t)col0 * DDIM;

    // warp tile: 32 (M) x 64 (N)
    const int wm = wid & 3, wn = wid >> 2;
    const int m0 = wm * 32, n0 = wn * 64;

    float acc[2][8][4];
    #pragma unroll
    for (int i = 0; i < 2; i++)
        #pragma unroll
        for (int j = 0; j < 8; j++)
            #pragma unroll
            for (int q = 0; q < 4; q++)
                acc[i][j][q] = 0.0f;

    // ldmatrix lane addressing
    const int arow = (lane & 7) + ((lane >> 3) & 1) * 8;
    const int acol = (lane >> 4) * 8;
    const int brow = (lane & 7) + ((lane >> 4) << 3);
    const int bcol = ((lane >> 3) & 1) * 8;

    load_stage(smb, 0, Ah_g, Al_g, Bh_g, Bl_g, 0, tid);
    CP_COMMIT();

    for (int it = 0; it < NCHUNK; it++) {
        if (it + 1 < NCHUNK) {
            load_stage(smb, (it + 1) & 1, Ah_g, Al_g, Bh_g, Bl_g,
                       (it + 1) * BK, tid);
            CP_COMMIT();
            CP_WAIT1();
        } else {
            CP_WAIT0();
        }
        __syncthreads();

        const uint32_t Ah = smb + (it & 1) * STAGE_B;
        const uint32_t Al = Ah + TILE_B;
        const uint32_t Bh = Al + TILE_B;
        const uint32_t Bl = Bh + TILE_B;

        #pragma unroll
        for (int ks = 0; ks < 2; ks++) {
            const int kb = ks * 16;
            uint32_t ahr[2][4], alr[2][4];
            #pragma unroll
            for (int mt = 0; mt < 2; mt++) {
                uint32_t off = (uint32_t)(m0 + mt * 16 + arow) * (TPAD * 2)
                             + (kb + acol) * 2;
                ldx4(ahr[mt], Ah + off);
                ldx4(alr[mt], Al + off);
            }
            // p-pair processing: 16 B-frag regs live, 24 MMAs in 3 passes
            #pragma unroll
            for (int pp = 0; pp < 2; pp++) {
                uint32_t rh[2][4], rl[2][4];
                #pragma unroll
                for (int q = 0; q < 2; q++) {
                    const int p = pp * 2 + q;
                    uint32_t off = (uint32_t)(n0 + p * 16 + brow) * (TPAD * 2)
                                 + (kb + bcol) * 2;
                    ldx4(rh[q], Bh + off);
                    ldx4(rl[q], Bl + off);
                }
                // pass 1: hi*hi -> 8 distinct accumulators
                #pragma unroll
                for (int mt = 0; mt < 2; mt++)
                    #pragma unroll
                    for (int q = 0; q < 2; q++) {
                        const int nt = (pp * 2 + q) * 2;
                        mma16816(acc[mt][nt],     ahr[mt], &rh[q][0]);
                        mma16816(acc[mt][nt + 1], ahr[mt], &rh[q][2]);
                    }
                // pass 2: hi*lo -> same 8 accs (reuse distance 8)
                #pragma unroll
                for (int mt = 0; mt < 2; mt++)
                    #pragma unroll
                    for (int q = 0; q < 2; q++) {
                        const int nt = (pp * 2 + q) * 2;
                        mma16816(acc[mt][nt],     ahr[mt], &rl[q][0]);
                        mma16816(acc[mt][nt + 1], ahr[mt], &rl[q][2]);
                    }
                // pass 3: lo*hi -> same 8 accs (reuse distance 8)
                #pragma unroll
                for (int mt = 0; mt < 2; mt++)
                    #pragma unroll
                    for (int q = 0; q < 2; q++) {
                        const int nt = (pp * 2 + q) * 2;
                        mma16816(acc[mt][nt],     alr[mt], &rh[q][0]);
                        mma16816(acc[mt][nt + 1], alr[mt], &rh[q][2]);
                    }
            }
        }
        __syncthreads();
    }

    // ---------------- epilogue: dump dots to smem dist tile ----------------
    float* ds = (float*)smem;
    const int g = lane >> 2;
    const int cl = (lane & 3) * 2;
    #pragma unroll
    for (int mt = 0; mt < 2; mt++) {
        const int rb = m0 + mt * 16 + g;
        #pragma unroll
        for (int nt = 0; nt < 8; nt++) {
            const int cb = n0 + nt * 8 + cl;
            ds[rb * DPAD + cb]           = acc[mt][nt][0];
            ds[rb * DPAD + cb + 1]       = acc[mt][nt][1];
            ds[(rb + 8) * DPAD + cb]     = acc[mt][nt][2];
            ds[(rb + 8) * DPAD + cb + 1] = acc[mt][nt][3];
        }
    }
    __syncthreads();

    const float INF = __int_as_float(0x7f800000);
    if (tid < 128) {
        // row pass: hardest positive + row min
        const int gi = row0 + tid;
        const float si = g_sq[gi];
        const int partner = (gi < NHALF) ? (gi + NHALF) : (gi - NHALF);
        float mn = INF;
        for (int c = 0; c < 128; c++) {
            const int gj = col0 + c;
            float dot = ds[tid * DPAD + c];
            float d2 = si + g_sq[gj] - 2.0f * dot;
            float dist = fmaxf(sqrtf(fmaxf(d2, 1e-14f)), 1e-7f);
            if (gj == partner) {
                g_pos[gi] = dist;
                g_pos[gj] = dist;
            } else if (gj != gi) {
                mn = fminf(mn, dist);
            }
        }
        atomicMin(&g_negmin_bits[gi], __float_as_uint(mn));
    } else if (!isdiag) {
        // col pass: col min (off-diagonal tiles only)
        const int c = tid - 128;
        const int gj = col0 + c;
        const float sj = g_sq[gj];
        const int partner = (gj < NHALF) ? (gj + NHALF) : (gj - NHALF);
        float mn = INF;
        for (int r = 0; r < 128; r++) {
            const int gi = row0 + r;
            float dot = ds[r * DPAD + c];
            float d2 = sj + g_sq[gi] - 2.0f * dot;
            float dist = fmaxf(sqrtf(fmaxf(d2, 1e-14f)), 1e-7f);
            if (gi != partner && gi != gj)
                mn = fminf(mn, dist);
        }
        atomicMin(&g_negmin_bits[gj], __float_as_uint(mn));
    }
}

// ---------------------------------------------------------------------------
// Kernel 3: finalize (single block)
// ---------------------------------------------------------------------------
__global__ void finalize_kernel(float* __restrict__ out) {
    const int t = threadIdx.x;  // 256 threads
    float sumdiff = 0.0f, sumrel = 0.0f, sumsq = 0.0f;
    int nrel = 0, good = 0;

    for (int r = t; r < NTOT; r += 256) {
        float pos = g_pos[r];
        float neg = __uint_as_float(g_negmin_bits[r]);
        float diff = pos - neg;
        float tl = fmaxf(diff + 0.1f, 0.0f);
        sumdiff += diff;
        if (tl > 1e-5f) { sumrel += tl; nrel++; }
        if (tl < 1e-5f) good++;
        sumsq += g_sq[r];
    }

    __shared__ float s_diff[256], s_rel[256], s_sq[256];
    __shared__ int   s_nrel[256], s_good[256];
    s_diff[t] = sumdiff; s_rel[t] = sumrel; s_sq[t] = sumsq;
    s_nrel[t] = nrel;    s_good[t] = good;
    __syncthreads();

    for (int stride = 128; stride > 0; stride >>= 1) {
        if (t < stride) {
            s_diff[t] += s_diff[t + stride];
            s_rel[t]  += s_rel[t + stride];
            s_sq[t]   += s_sq[t + stride];
            s_nrel[t] += s_nrel[t + stride];
            s_good[t] += s_good[t + stride];
        }
        __syncthreads();
    }

    if (t == 0) {
        int n_rel = s_nrel[0] > 0 ? s_nrel[0] : 1;
        out[0] = s_rel[0] / (float)n_rel;
        out[1] = s_diff[0] / (float)NTOT;
        out[2] = (float)s_good[0];
        out[3] = (float)(NTOT - s_good[0]);
        out[4] = sqrtf(s_sq[0] / (float)NTOT);
    }
}

// ---------------------------------------------------------------------------
extern "C" void kernel_launch(void* const* d_in, const int* in_sizes, int n_in,
                              void* d_out, int out_size) {
    const float* h1 = (const float*)d_in[0];
    const float* h2 = (const float*)d_in[1];
    float* out = (float*)d_out;

    cudaFuncSetAttribute(gemm_dist_kernel,
                         cudaFuncAttributeMaxDynamicSharedMemorySize, SM_TOTAL);

    prep_kernel<<<NTOT, 128>>>(h1, h2);
    gemm_dist_kernel<<<NBLK, 256, SM_TOTAL>>>();
    finalize_kernel<<<1, 256>>>(out);
}

// round 10
// speedup vs baseline: 1.0245x; 1.0030x over previous
#include <cuda_runtime.h>
#include <cuda_bf16.h>
#include <stdint.h>
#include <math.h>

#define NHALF 2048
#define NTOT  4096
#define DDIM  512

#define BM 128
#define BN 128
#define BK 32
#define NCHUNK (DDIM / BK)   // 16
#define NTILE 32
#define NBLK 528             // upper-triangle tiles

#define TPAD 40                      // bf16 elements per smem tile row (80 B)
#define TILE_B (128 * TPAD * 2)      // 10240 B per tile
#define STAGE_B (4 * TILE_B)         // Ah, Al, Bh, Bl
#define SM_TOTAL (2 * STAGE_B)       // 81920 B (dist tile overlays this)
#define DPAD 133                     // fp32 dist tile row stride

// ---------------- device globals ----------------
__device__ float          g_sq[NTOT];
__device__ unsigned       g_negmin_bits[NTOT];
__device__ float          g_pos[NTOT];
__device__ __nv_bfloat16  g_hi[NTOT * DDIM];
__device__ __nv_bfloat16  g_lo[NTOT * DDIM];

// ---------------- helpers ----------------
__device__ __forceinline__ uint32_t smem_u32(const void* p) {
    uint32_t a;
    asm("{ .reg .u64 t; cvta.to.shared.u64 t, %1; cvt.u32.u64 %0, t; }"
        : "=r"(a) : "l"(p));
    return a;
}
__device__ __forceinline__ void cp16(uint32_t dst, const void* src) {
    asm volatile("cp.async.cg.shared.global [%0], [%1], 16;"
                 :: "r"(dst), "l"(src));
}
#define CP_COMMIT() asm volatile("cp.async.commit_group;" ::: "memory")
#define CP_WAIT1()  asm volatile("cp.async.wait_group 1;" ::: "memory")
#define CP_WAIT0()  asm volatile("cp.async.wait_group 0;" ::: "memory")

__device__ __forceinline__ void ldx4(uint32_t* r, uint32_t addr) {
    asm volatile("ldmatrix.sync.aligned.m8n8.x4.shared.b16 {%0,%1,%2,%3}, [%4];"
                 : "=r"(r[0]), "=r"(r[1]), "=r"(r[2]), "=r"(r[3]) : "r"(addr));
}
__device__ __forceinline__ void mma16816(float* d, const uint32_t* a,
                                         const uint32_t* b) {
    asm volatile(
        "mma.sync.aligned.m16n8k16.row.col.f32.bf16.bf16.f32 "
        "{%0,%1,%2,%3}, {%4,%5,%6,%7}, {%8,%9}, {%0,%1,%2,%3};"
        : "+f"(d[0]), "+f"(d[1]), "+f"(d[2]), "+f"(d[3])
        : "r"(a[0]), "r"(a[1]), "r"(a[2]), "r"(a[3]), "r"(b[0]), "r"(b[1]));
}

// ---------------------------------------------------------------------------
// Kernel 1: row sums of squares + bf16 hi/lo split + scratch reset
// 512 blocks x 256 threads; one warp per row, 8 rows per block
// ---------------------------------------------------------------------------
__global__ __launch_bounds__(256)
void prep_kernel(const float* __restrict__ h1,
                 const float* __restrict__ h2) {
    const int wid = threadIdx.x >> 5, lane = threadIdx.x & 31;
    const int r = blockIdx.x * 8 + wid;
    const float* src = (r < NHALF) ? (h1 + (size_t)r * DDIM)
                                   : (h2 + (size_t)(r - NHALF) * DDIM);
    float s = 0.0f;
    #pragma unroll
    for (int u = 0; u < 4; u++) {
        float4 v = ((const float4*)src)[lane + 32 * u];
        s += v.x * v.x + v.y * v.y + v.z * v.z + v.w * v.w;

        __nv_bfloat16 a0 = __float2bfloat16(v.x);
        __nv_bfloat16 a1 = __float2bfloat16(v.y);
        __nv_bfloat16 a2 = __float2bfloat16(v.z);
        __nv_bfloat16 a3 = __float2bfloat16(v.w);
        __nv_bfloat16 l0 = __float2bfloat16(v.x - __bfloat162float(a0));
        __nv_bfloat16 l1 = __float2bfloat16(v.y - __bfloat162float(a1));
        __nv_bfloat16 l2 = __float2bfloat16(v.z - __bfloat162float(a2));
        __nv_bfloat16 l3 = __float2bfloat16(v.w - __bfloat162float(a3));

        size_t base = (size_t)r * DDIM + 4 * (lane + 32 * u);
        __nv_bfloat162* gh = (__nv_bfloat162*)(g_hi + base);
        gh[0] = __nv_bfloat162(a0, a1);
        gh[1] = __nv_bfloat162(a2, a3);
        __nv_bfloat162* gl = (__nv_bfloat162*)(g_lo + base);
        gl[0] = __nv_bfloat162(l0, l1);
        gl[1] = __nv_bfloat162(l2, l3);
    }

    #pragma unroll
    for (int off = 16; off > 0; off >>= 1)
        s += __shfl_xor_sync(0xffffffffu, s, off);

    if (lane == 0) {
        g_sq[r] = s;
        g_negmin_bits[r] = 0x7f800000u;  // +inf
        g_pos[r] = 0.0f;
    }
}

// ---------------------------------------------------------------------------
// async-load one pipeline stage (4 tiles of 128 x 32 bf16)
// ---------------------------------------------------------------------------
__device__ __forceinline__ void load_stage(uint32_t smb, int stage,
                                           const __nv_bfloat16* ah,
                                           const __nv_bfloat16* al,
                                           const __nv_bfloat16* bh,
                                           const __nv_bfloat16* bl,
                                           int k0, int tid) {
    const __nv_bfloat16* srcs[4] = {ah, al, bh, bl};
    uint32_t base = smb + stage * STAGE_B;
    #pragma unroll
    for (int t = 0; t < 4; t++) {
        #pragma unroll
        for (int i = 0; i < 2; i++) {
            int chunk = tid * 2 + i;       // 0..511
            int r = chunk >> 2;            // 0..127
            int c = chunk & 3;             // 16B chunk within 64B row
            cp16(base + t * TILE_B + r * (TPAD * 2) + c * 16,
                 srcs[t] + (size_t)r * DDIM + k0 + c * 8);
        }
    }
}

// ---------------------------------------------------------------------------
// Kernel 2: bf16x3 mma.sync X*X^T (upper triangle) + fused distance epilogue
// ---------------------------------------------------------------------------
__global__ __launch_bounds__(256, 2)
void gemm_dist_kernel() {
    extern __shared__ char smem[];
    const uint32_t smb = smem_u32(smem);
    const int tid = threadIdx.x;
    const int wid = tid >> 5, lane = tid & 31;

    // decode upper-triangle tile index
    int t = blockIdx.x;
    int bi = 0;
    while (t >= NTILE - bi) { t -= NTILE - bi; bi++; }
    const int bj = bi + t;
    const int row0 = bi * BM;
    const int col0 = bj * BN;
    const bool isdiag = (bi == bj);

    const __nv_bfloat16* Ah_g = g_hi + (size_t)row0 * DDIM;
    const __nv_bfloat16* Al_g = g_lo + (size_t)row0 * DDIM;
    const __nv_bfloat16* Bh_g = g_hi + (size_t)col0 * DDIM;
    const __nv_bfloat16* Bl_g = g_lo + (size_t)col0 * DDIM;

    // warp tile: 32 (M) x 64 (N)
    const int wm = wid & 3, wn = wid >> 2;
    const int m0 = wm * 32, n0 = wn * 64;

    float acc[2][8][4];
    #pragma unroll
    for (int i = 0; i < 2; i++)
        #pragma unroll
        for (int j = 0; j < 8; j++)
            #pragma unroll
            for (int q = 0; q < 4; q++)
                acc[i][j][q] = 0.0f;

    // ldmatrix lane addressing
    const int arow = (lane & 7) + ((lane >> 3) & 1) * 8;
    const int acol = (lane >> 4) * 8;
    const int brow = (lane & 7) + ((lane >> 4) << 3);
    const int bcol = ((lane >> 3) & 1) * 8;

    load_stage(smb, 0, Ah_g, Al_g, Bh_g, Bl_g, 0, tid);
    CP_COMMIT();

    for (int it = 0; it < NCHUNK; it++) {
        if (it + 1 < NCHUNK) {
            load_stage(smb, (it + 1) & 1, Ah_g, Al_g, Bh_g, Bl_g,
                       (it + 1) * BK, tid);
            CP_COMMIT();
            CP_WAIT1();
        } else {
            CP_WAIT0();
        }
        __syncthreads();

        const uint32_t Ah = smb + (it & 1) * STAGE_B;
        const uint32_t Al = Ah + TILE_B;
        const uint32_t Bh = Al + TILE_B;
        const uint32_t Bl = Bh + TILE_B;

        #pragma unroll
        for (int ks = 0; ks < 2; ks++) {
            const int kb = ks * 16;
            uint32_t ahr[2][4], alr[2][4];
            #pragma unroll
            for (int mt = 0; mt < 2; mt++) {
                uint32_t off = (uint32_t)(m0 + mt * 16 + arow) * (TPAD * 2)
                             + (kb + acol) * 2;
                ldx4(ahr[mt], Ah + off);
                ldx4(alr[mt], Al + off);
            }
            // stream B per 16-col group to keep register pressure low
            #pragma unroll
            for (int p = 0; p < 4; p++) {
                uint32_t off = (uint32_t)(n0 + p * 16 + brow) * (TPAD * 2)
                             + (kb + bcol) * 2;
                uint32_t rh[4], rl[4];
                ldx4(rh, Bh + off);
                ldx4(rl, Bl + off);
                uint32_t b0h[2] = {rh[0], rh[1]}, b1h[2] = {rh[2], rh[3]};
                uint32_t b0l[2] = {rl[0], rl[1]}, b1l[2] = {rl[2], rl[3]};
                #pragma unroll
                for (int mt = 0; mt < 2; mt++) {
                    mma16816(acc[mt][2 * p],     ahr[mt], b0h);
                    mma16816(acc[mt][2 * p + 1], ahr[mt], b1h);
                    mma16816(acc[mt][2 * p],     ahr[mt], b0l);
                    mma16816(acc[mt][2 * p + 1], ahr[mt], b1l);
                    mma16816(acc[mt][2 * p],     alr[mt], b0h);
                    mma16816(acc[mt][2 * p + 1], alr[mt], b1h);
                }
            }
        }
        __syncthreads();
    }

    // ---------------- epilogue: dump dots to smem dist tile ----------------
    float* ds = (float*)smem;
    const int g = lane >> 2;
    const int cl = (lane & 3) * 2;
    #pragma unroll
    for (int mt = 0; mt < 2; mt++) {
        const int rb = m0 + mt * 16 + g;
        #pragma unroll
        for (int nt = 0; nt < 8; nt++) {
            const int cb = n0 + nt * 8 + cl;
            ds[rb * DPAD + cb]           = acc[mt][nt][0];
            ds[rb * DPAD + cb + 1]       = acc[mt][nt][1];
            ds[(rb + 8) * DPAD + cb]     = acc[mt][nt][2];
            ds[(rb + 8) * DPAD + cb + 1] = acc[mt][nt][3];
        }
    }
    __syncthreads();

    const float INF = __int_as_float(0x7f800000);
    if (tid < 128) {
        // row pass: hardest positive + row min
        const int gi = row0 + tid;
        const float si = g_sq[gi];
        const int partner = (gi < NHALF) ? (gi + NHALF) : (gi - NHALF);
        float mn = INF;
        #pragma unroll 4
        for (int c = 0; c < 128; c++) {
            const int gj = col0 + c;
            float dot = ds[tid * DPAD + c];
            float d2 = si + g_sq[gj] - 2.0f * dot;
            float dist = fmaxf(sqrtf(fmaxf(d2, 1e-14f)), 1e-7f);
            if (gj == partner) {
                g_pos[gi] = dist;
                g_pos[gj] = dist;
            } else if (gj != gi) {
                mn = fminf(mn, dist);
            }
        }
        atomicMin(&g_negmin_bits[gi], __float_as_uint(mn));
    } else if (!isdiag) {
        // col pass: col min (off-diagonal tiles only)
        const int c = tid - 128;
        const int gj = col0 + c;
        const float sj = g_sq[gj];
        const int partner = (gj < NHALF) ? (gj + NHALF) : (gj - NHALF);
        float mn = INF;
        #pragma unroll 4
        for (int r = 0; r < 128; r++) {
            const int gi = row0 + r;
            float dot = ds[r * DPAD + c];
            float d2 = sj + g_sq[gi] - 2.0f * dot;
            float dist = fmaxf(sqrtf(fmaxf(d2, 1e-14f)), 1e-7f);
            if (gi != partner && gi != gj)
                mn = fminf(mn, dist);
        }
        atomicMin(&g_negmin_bits[gj], __float_as_uint(mn));
    }
}

// ---------------------------------------------------------------------------
// Kernel 3: finalize (single block, warp-shuffle reductions)
// ---------------------------------------------------------------------------
__global__ void finalize_kernel(float* __restrict__ out) {
    const int t = threadIdx.x;  // 256 threads
    float sumdiff = 0.0f, sumrel = 0.0f, sumsq = 0.0f;
    int nrel = 0, good = 0;

    #pragma unroll 4
    for (int r = t; r < NTOT; r += 256) {
        float pos = g_pos[r];
        float neg = __uint_as_float(g_negmin_bits[r]);
        float diff = pos - neg;
        float tl = fmaxf(diff + 0.1f, 0.0f);
        sumdiff += diff;
        if (tl > 1e-5f) { sumrel += tl; nrel++; }
        if (tl < 1e-5f) good++;
        sumsq += g_sq[r];
    }

    #pragma unroll
    for (int off = 16; off > 0; off >>= 1) {
        sumdiff += __shfl_xor_sync(0xffffffffu, sumdiff, off);
        sumrel  += __shfl_xor_sync(0xffffffffu, sumrel, off);
        sumsq   += __shfl_xor_sync(0xffffffffu, sumsq, off);
        nrel    += __shfl_xor_sync(0xffffffffu, nrel, off);
        good    += __shfl_xor_sync(0xffffffffu, good, off);
    }

    __shared__ float s_diff[8], s_rel[8], s_sq[8];
    __shared__ int   s_nrel[8], s_good[8];
    const int wid = t >> 5, lane = t & 31;
    if (lane == 0) {
        s_diff[wid] = sumdiff; s_rel[wid] = sumrel; s_sq[wid] = sumsq;
        s_nrel[wid] = nrel;    s_good[wid] = good;
    }
    __syncthreads();

    if (t == 0) {
        float td = 0, tr = 0, tq = 0; int tn = 0, tg = 0;
        #pragma unroll
        for (int w = 0; w < 8; w++) {
            td += s_diff[w]; tr += s_rel[w]; tq += s_sq[w];
            tn += s_nrel[w]; tg += s_good[w];
        }
        int n_rel = tn > 0 ? tn : 1;
        out[0] = tr / (float)n_rel;
        out[1] = td / (float)NTOT;
        out[2] = (float)tg;
        out[3] = (float)(NTOT - tg);
        out[4] = sqrtf(tq / (float)NTOT);
    }
}

// ---------------------------------------------------------------------------
extern "C" void kernel_launch(void* const* d_in, const int* in_sizes, int n_in,
                              void* d_out, int out_size) {
    const float* h1 = (const float*)d_in[0];
    const float* h2 = (const float*)d_in[1];
    float* out = (float*)d_out;

    cudaFuncSetAttribute(gemm_dist_kernel,
                         cudaFuncAttributeMaxDynamicSharedMemorySize, SM_TOTAL);

    prep_kernel<<<NTOT / 8, 256>>>(h1, h2);
    gemm_dist_kernel<<<NBLK, 256, SM_TOTAL>>>();
    finalize_kernel<<<1, 256>>>(out);
}

// round 11
// speedup vs baseline: 1.3664x; 1.3337x over previous
#include <cuda_runtime.h>
#include <cuda_bf16.h>
#include <cuda_fp16.h>
#include <stdint.h>
#include <math.h>

#define NHALF 2048
#define NTOT  4096
#define DDIM  512

#define BM 128
#define BN 128
#define BK 32
#define NCHUNK (DDIM / BK)   // 16
#define NTILE 32
#define NBLK 528             // upper-triangle tiles

#define TPAD 40                      // bf16 per smem tile row (80 B)
#define TILE_B (128 * TPAD * 2)      // 10240 B
#define STAGE_B (2 * TILE_B)         // Ah, Bh only
#define SM_TOTAL (2 * STAGE_B)       // 40960 B (fp16 dist tile overlays)
#define DS_STRIDE 136                // halves per epilogue smem row

#define MARGIN 0.15f

// ---------------- device globals ----------------
__device__ float          g_sq[NTOT];
__device__ float          g_pos[NTOT];
__device__ float          g_neg[NTOT];
__device__ __nv_bfloat16  g_hi[NTOT * DDIM];
__device__ __half         g_dist[NTOT * NTOT];   // 32 MB approx dists

// ---------------- helpers ----------------
__device__ __forceinline__ uint32_t smem_u32(const void* p) {
    uint32_t a;
    asm("{ .reg .u64 t; cvta.to.shared.u64 t, %1; cvt.u32.u64 %0, t; }"
        : "=r"(a) : "l"(p));
    return a;
}
__device__ __forceinline__ void cp16(uint32_t dst, const void* src) {
    asm volatile("cp.async.cg.shared.global [%0], [%1], 16;"
                 :: "r"(dst), "l"(src));
}
#define CP_COMMIT() asm volatile("cp.async.commit_group;" ::: "memory")
#define CP_WAIT1()  asm volatile("cp.async.wait_group 1;" ::: "memory")
#define CP_WAIT0()  asm volatile("cp.async.wait_group 0;" ::: "memory")

__device__ __forceinline__ void ldx4(uint32_t* r, uint32_t addr) {
    asm volatile("ldmatrix.sync.aligned.m8n8.x4.shared.b16 {%0,%1,%2,%3}, [%4];"
                 : "=r"(r[0]), "=r"(r[1]), "=r"(r[2]), "=r"(r[3]) : "r"(addr));
}
__device__ __forceinline__ void mma16816(float* d, const uint32_t* a,
                                         const uint32_t* b) {
    asm volatile(
        "mma.sync.aligned.m16n8k16.row.col.f32.bf16.bf16.f32 "
        "{%0,%1,%2,%3}, {%4,%5,%6,%7}, {%8,%9}, {%0,%1,%2,%3};"
        : "+f"(d[0]), "+f"(d[1]), "+f"(d[2]), "+f"(d[3])
        : "r"(a[0]), "r"(a[1]), "r"(a[2]), "r"(a[3]), "r"(b[0]), "r"(b[1]));
}
__device__ __forceinline__ float clamp_dist(float d2) {
    return fmaxf(sqrtf(fmaxf(d2, 1e-14f)), 1e-7f);
}

// ---------------------------------------------------------------------------
// Kernel 1: per-pair sums of squares, exact positive dist, bf16-hi split
// grid 256 x 256 threads; warp w handles pair (w, w+2048)
// ---------------------------------------------------------------------------
__global__ __launch_bounds__(256)
void prep_kernel(const float* __restrict__ h1,
                 const float* __restrict__ h2) {
    const int wid = threadIdx.x >> 5, lane = threadIdx.x & 31;
    const int r = blockIdx.x * 8 + wid;      // 0..2047
    const float* xr = h1 + (size_t)r * DDIM;
    const float* yr = h2 + (size_t)r * DDIM;

    float s1 = 0.0f, s2 = 0.0f, dt = 0.0f;
    #pragma unroll
    for (int u = 0; u < 4; u++) {
        const int fi = lane + 32 * u;
        float4 xv = ((const float4*)xr)[fi];
        float4 yv = ((const float4*)yr)[fi];
        s1 += xv.x * xv.x + xv.y * xv.y + xv.z * xv.z + xv.w * xv.w;
        s2 += yv.x * yv.x + yv.y * yv.y + yv.z * yv.z + yv.w * yv.w;
        dt += xv.x * yv.x + xv.y * yv.y + xv.z * yv.z + xv.w * yv.w;

        size_t bx = (size_t)r * DDIM + 4 * fi;
        __nv_bfloat162* gx = (__nv_bfloat162*)(g_hi + bx);
        gx[0] = __nv_bfloat162(__float2bfloat16(xv.x), __float2bfloat16(xv.y));
        gx[1] = __nv_bfloat162(__float2bfloat16(xv.z), __float2bfloat16(xv.w));
        __nv_bfloat162* gy = (__nv_bfloat162*)(g_hi + bx + (size_t)NHALF * DDIM);
        gy[0] = __nv_bfloat162(__float2bfloat16(yv.x), __float2bfloat16(yv.y));
        gy[1] = __nv_bfloat162(__float2bfloat16(yv.z), __float2bfloat16(yv.w));
    }

    #pragma unroll
    for (int off = 16; off > 0; off >>= 1) {
        s1 += __shfl_xor_sync(0xffffffffu, s1, off);
        s2 += __shfl_xor_sync(0xffffffffu, s2, off);
        dt += __shfl_xor_sync(0xffffffffu, dt, off);
    }

    if (lane == 0) {
        g_sq[r] = s1;
        g_sq[r + NHALF] = s2;
        float pos = clamp_dist(s1 + s2 - 2.0f * dt);
        g_pos[r] = pos;
        g_pos[r + NHALF] = pos;
    }
}

// ---------------------------------------------------------------------------
// async-load one pipeline stage (2 tiles of 128 x 32 bf16: Ah, Bh)
// ---------------------------------------------------------------------------
__device__ __forceinline__ void load_stage(uint32_t smb, int stage,
                                           const __nv_bfloat16* ah,
                                           const __nv_bfloat16* bh,
                                           int k0, int tid) {
    const __nv_bfloat16* srcs[2] = {ah, bh};
    uint32_t base = smb + stage * STAGE_B;
    #pragma unroll
    for (int t = 0; t < 2; t++) {
        #pragma unroll
        for (int i = 0; i < 2; i++) {
            int chunk = tid * 2 + i;       // 0..511
            int r = chunk >> 2;            // 0..127
            int c = chunk & 3;             // 16B chunk within 64B row
            cp16(base + t * TILE_B + r * (TPAD * 2) + c * 16,
                 srcs[t] + (size_t)r * DDIM + k0 + c * 8);
        }
    }
}

// ---------------------------------------------------------------------------
// Kernel 2: hi-only bf16 mma.sync X*X^T (upper triangle); stores approx
// distances (fp16) for the tile and its transpose to g_dist
// ---------------------------------------------------------------------------
__global__ __launch_bounds__(256, 2)
void gemm_dist_kernel() {
    extern __shared__ char smem[];
    const uint32_t smb = smem_u32(smem);
    const int tid = threadIdx.x;
    const int wid = tid >> 5, lane = tid & 31;

    // decode upper-triangle tile index
    int t = blockIdx.x;
    int bi = 0;
    while (t >= NTILE - bi) { t -= NTILE - bi; bi++; }
    const int bj = bi + t;
    const int row0 = bi * BM;
    const int col0 = bj * BN;
    const bool isdiag = (bi == bj);

    const __nv_bfloat16* Ah_g = g_hi + (size_t)row0 * DDIM;
    const __nv_bfloat16* Bh_g = g_hi + (size_t)col0 * DDIM;

    // warp tile: 32 (M) x 64 (N)
    const int wm = wid & 3, wn = wid >> 2;
    const int m0 = wm * 32, n0 = wn * 64;

    float acc[2][8][4];
    #pragma unroll
    for (int i = 0; i < 2; i++)
        #pragma unroll
        for (int j = 0; j < 8; j++)
            #pragma unroll
            for (int q = 0; q < 4; q++)
                acc[i][j][q] = 0.0f;

    const int arow = (lane & 7) + ((lane >> 3) & 1) * 8;
    const int acol = (lane >> 4) * 8;
    const int brow = (lane & 7) + ((lane >> 4) << 3);
    const int bcol = ((lane >> 3) & 1) * 8;

    load_stage(smb, 0, Ah_g, Bh_g, 0, tid);
    CP_COMMIT();

    for (int it = 0; it < NCHUNK; it++) {
        if (it + 1 < NCHUNK) {
            load_stage(smb, (it + 1) & 1, Ah_g, Bh_g, (it + 1) * BK, tid);
            CP_COMMIT();
            CP_WAIT1();
        } else {
            CP_WAIT0();
        }
        __syncthreads();

        const uint32_t Ah = smb + (it & 1) * STAGE_B;
        const uint32_t Bh = Ah + TILE_B;

        #pragma unroll
        for (int ks = 0; ks < 2; ks++) {
            const int kb = ks * 16;
            uint32_t ahr[2][4];
            #pragma unroll
            for (int mt = 0; mt < 2; mt++) {
                uint32_t off = (uint32_t)(m0 + mt * 16 + arow) * (TPAD * 2)
                             + (kb + acol) * 2;
                ldx4(ahr[mt], Ah + off);
            }
            #pragma unroll
            for (int p = 0; p < 4; p++) {
                uint32_t off = (uint32_t)(n0 + p * 16 + brow) * (TPAD * 2)
                             + (kb + bcol) * 2;
                uint32_t rh[4];
                ldx4(rh, Bh + off);
                uint32_t b0h[2] = {rh[0], rh[1]}, b1h[2] = {rh[2], rh[3]};
                #pragma unroll
                for (int mt = 0; mt < 2; mt++) {
                    mma16816(acc[mt][2 * p],     ahr[mt], b0h);
                    mma16816(acc[mt][2 * p + 1], ahr[mt], b1h);
                }
            }
        }
        __syncthreads();
    }

    // ------------- epilogue: dist(fp16) into smem tile -------------
    __half* ds = (__half*)smem;
    const int g = lane >> 2;
    const int cl = (lane & 3) * 2;
    #pragma unroll
    for (int mt = 0; mt < 2; mt++) {
        const int rb = m0 + mt * 16 + g;
        #pragma unroll
        for (int nt = 0; nt < 8; nt++) {
            const int cb = n0 + nt * 8 + cl;
            #pragma unroll
            for (int h = 0; h < 2; h++) {
                const int rr = rb + h * 8;
                const float si = g_sq[row0 + rr];
                float d0 = clamp_dist(si + g_sq[col0 + cb]
                                      - 2.0f * acc[mt][nt][2 * h]);
                float d1 = clamp_dist(si + g_sq[col0 + cb + 1]
                                      - 2.0f * acc[mt][nt][2 * h + 1]);
                *(__half2*)&ds[rr * DS_STRIDE + cb] =
                    __floats2half2_rn(d0, d1);
            }
        }
    }
    __syncthreads();

    // row-orientation block: [row0..][col0..]
    {
        const int rb = tid >> 1, seg = tid & 1;
        const uint4* src = (const uint4*)&ds[rb * DS_STRIDE + seg * 64];
        uint4* dst = (uint4*)&g_dist[(size_t)(row0 + rb) * NTOT + col0 + seg * 64];
        #pragma unroll
        for (int q = 0; q < 8; q++) dst[q] = src[q];
    }
    // transposed block (off-diagonal only): [col0..][row0..]
    if (!isdiag) {
        const int c = tid >> 1, seg = tid & 1;
        __half v[64];
        #pragma unroll 8
        for (int k = 0; k < 64; k++)
            v[k] = ds[(seg * 64 + k) * DS_STRIDE + c];
        uint4* dst = (uint4*)&g_dist[(size_t)(col0 + c) * NTOT + row0 + seg * 64];
        const uint4* sv = (const uint4*)v;
        #pragma unroll
        for (int q = 0; q < 8; q++) dst[q] = sv[q];
    }
}

// ---------------------------------------------------------------------------
// Kernel 3: refine — per-row approx min scan + exact recompute of candidates
// grid 512 x 256 (8 warps); warp = one row
// ---------------------------------------------------------------------------
__global__ __launch_bounds__(256)
void refine_kernel(const float* __restrict__ h1,
                   const float* __restrict__ h2) {
    const int wid = threadIdx.x >> 5, lane = threadIdx.x & 31;
    const int r = blockIdx.x * 8 + wid;          // 0..4095
    const int partner = r ^ NHALF;
    const float INF = __int_as_float(0x7f800000);

    const __half* row = g_dist + (size_t)r * NTOT;

    // pass 1: approximate min (excluding diag & partner)
    float mn = INF;
    const uint4* row4 = (const uint4*)row;
    #pragma unroll
    for (int it = 0; it < 16; it++) {
        const int idx = it * 32 + lane;          // uint4 index
        const int j0 = idx * 8;
        uint4 u = row4[idx];
        const __half2* hp = (const __half2*)&u;
        if (((unsigned)(r - j0) < 8u) || ((unsigned)(partner - j0) < 8u)) {
            #pragma unroll
            for (int h = 0; h < 4; h++) {
                float2 f = __half22float2(hp[h]);
                int j = j0 + 2 * h;
                if (j != r && j != partner) mn = fminf(mn, f.x);
                if (j + 1 != r && j + 1 != partner) mn = fminf(mn, f.y);
            }
        } else {
            #pragma unroll
            for (int h = 0; h < 4; h++) {
                float2 f = __half22float2(hp[h]);
                mn = fminf(mn, fminf(f.x, f.y));
            }
        }
    }
    #pragma unroll
    for (int off = 16; off > 0; off >>= 1)
        mn = fminf(mn, __shfl_xor_sync(0xffffffffu, mn, off));
    const float thresh = mn + MARGIN;

    // preload this row's fp32 data (16 dims per lane)
    const float* xr = (r < NHALF) ? h1 + (size_t)r * DDIM
                                  : h2 + (size_t)(r - NHALF) * DDIM;
    float4 x4[4];
    #pragma unroll
    for (int q = 0; q < 4; q++)
        x4[q] = ((const float4*)xr)[lane * 4 + q];
    const float sqr = g_sq[r];

    // pass 2: candidates -> exact recompute
    float ex = INF;
    const __half2* row2 = (const __half2*)row;
    for (int it = 0; it < 64; it++) {
        const int j2 = (it * 32 + lane) * 2;
        float2 f = __half22float2(row2[it * 32 + lane]);
        bool c0 = (f.x <= thresh) && (j2 != r) && (j2 != partner);
        bool c1 = (f.y <= thresh) && (j2 + 1 != r) && (j2 + 1 != partner);
        unsigned act = __ballot_sync(0xffffffffu, c0 || c1);
        unsigned pk = (c0 ? 1u : 0u) | (c1 ? 2u : 0u);
        while (act) {
            const int b = __ffs(act) - 1;
            act &= act - 1;
            const unsigned pb = __shfl_sync(0xffffffffu, pk, b);
            const int jb = __shfl_sync(0xffffffffu, j2, b);
            #pragma unroll
            for (int s = 0; s < 2; s++) {
                if (!(pb & (1u << s))) continue;
                const int j = jb + s;
                const float* yr = (j < NHALF) ? h1 + (size_t)j * DDIM
                                              : h2 + (size_t)(j - NHALF) * DDIM;
                float dot = 0.0f;
                #pragma unroll
                for (int q = 0; q < 4; q++) {
                    float4 yv = ((const float4*)yr)[lane * 4 + q];
                    dot += x4[q].x * yv.x + x4[q].y * yv.y
                         + x4[q].z * yv.z + x4[q].w * yv.w;
                }
                #pragma unroll
                for (int off = 16; off > 0; off >>= 1)
                    dot += __shfl_xor_sync(0xffffffffu, dot, off);
                ex = fminf(ex, clamp_dist(sqr + g_sq[j] - 2.0f * dot));
            }
        }
    }
    if (lane == 0) g_neg[r] = ex;
}

// ---------------------------------------------------------------------------
// Kernel 4: finalize (single block)
// ---------------------------------------------------------------------------
__global__ void finalize_kernel(float* __restrict__ out) {
    const int t = threadIdx.x;  // 256 threads
    float sumdiff = 0.0f, sumrel = 0.0f, sumsq = 0.0f;
    int nrel = 0, good = 0;

    #pragma unroll 4
    for (int r = t; r < NTOT; r += 256) {
        float diff = g_pos[r] - g_neg[r];
        float tl = fmaxf(diff + 0.1f, 0.0f);
        sumdiff += diff;
        if (tl > 1e-5f) { sumrel += tl; nrel++; }
        if (tl < 1e-5f) good++;
        sumsq += g_sq[r];
    }

    #pragma unroll
    for (int off = 16; off > 0; off >>= 1) {
        sumdiff += __shfl_xor_sync(0xffffffffu, sumdiff, off);
        sumrel  += __shfl_xor_sync(0xffffffffu, sumrel, off);
        sumsq   += __shfl_xor_sync(0xffffffffu, sumsq, off);
        nrel    += __shfl_xor_sync(0xffffffffu, nrel, off);
        good    += __shfl_xor_sync(0xffffffffu, good, off);
    }

    __shared__ float s_diff[8], s_rel[8], s_sq[8];
    __shared__ int   s_nrel[8], s_good[8];
    const int wid = t >> 5, lane = t & 31;
    if (lane == 0) {
        s_diff[wid] = sumdiff; s_rel[wid] = sumrel; s_sq[wid] = sumsq;
        s_nrel[wid] = nrel;    s_good[wid] = good;
    }
    __syncthreads();

    if (t == 0) {
        float td = 0, tr = 0, tq = 0; int tn = 0, tg = 0;
        #pragma unroll
        for (int w = 0; w < 8; w++) {
            td += s_diff[w]; tr += s_rel[w]; tq += s_sq[w];
            tn += s_nrel[w]; tg += s_good[w];
        }
        int n_rel = tn > 0 ? tn : 1;
        out[0] = tr / (float)n_rel;
        out[1] = td / (float)NTOT;
        out[2] = (float)tg;
        out[3] = (float)(NTOT - tg);
        out[4] = sqrtf(tq / (float)NTOT);
    }
}

// ---------------------------------------------------------------------------
extern "C" void kernel_launch(void* const* d_in, const int* in_sizes, int n_in,
                              void* d_out, int out_size) {
    const float* h1 = (const float*)d_in[0];
    const float* h2 = (const float*)d_in[1];
    float* out = (float*)d_out;

    cudaFuncSetAttribute(gemm_dist_kernel,
                         cudaFuncAttributeMaxDynamicSharedMemorySize, SM_TOTAL);

    prep_kernel<<<NHALF / 8, 256>>>(h1, h2);
    gemm_dist_kernel<<<NBLK, 256, SM_TOTAL>>>();
    refine_kernel<<<NTOT / 8, 256>>>(h1, h2);
    finalize_kernel<<<1, 256>>>(out);
}